// round 6
// baseline (speedup 1.0000x reference)
#include <cuda_runtime.h>
#include <math.h>
#include <float.h>

// Problem constants
#define NN    6144
#define FEATN 512
#define HIDN  256
#define KMN   50
#define KNNN  20
#define THRF  0.1f
// spatial: exp(-d2 / (2*50^2)) = exp(-d2/5000)
#define INV2SD2 (1.0f/5000.0f)

// ---------------- device scratch (static; no allocation allowed) ----------------
__device__ float g_fn[NN * FEATN];                 // normalized features
__device__ float g_adj[(size_t)NN * NN];           // dense adj (pre-mask), 151MB
__device__ float g_xw1[NN * HIDN];                 // X @ W1
__device__ float g_acc[NN * HIDN];                 // GCN1 accumulator -> h
__device__ float g_t1[NN * KMN];                   // h @ W2
__device__ float g_sacc[NN * KMN];                 // GCN2 accumulator
__device__ float g_t2[NN * KMN];                   // adj @ S
__device__ float g_deg[NN];
__device__ float g_dinv[NN];
__device__ int   g_idx[NN * KNNN];
__device__ float g_val[NN * KNNN];
__device__ float g_Ac[KMN * KMN];
__device__ float g_loss;
__device__ float g_E;

// ---------------- 1. normalize rows of features ----------------
__global__ __launch_bounds__(128) void k_prep(const float* __restrict__ X) {
    int row = blockIdx.x, t = threadIdx.x;
    const float* xr = X + row * FEATN;
    float ss = 0.f;
    for (int f = t; f < FEATN; f += 128) { float v = xr[f]; ss += v * v; }
    for (int o = 16; o > 0; o >>= 1) ss += __shfl_down_sync(0xffffffffu, ss, o);
    __shared__ float red[4];
    __shared__ float sinv;
    if ((t & 31) == 0) red[t >> 5] = ss;
    __syncthreads();
    if (t == 0) {
        float s = red[0] + red[1] + red[2] + red[3];
        sinv = 1.0f / fmaxf(sqrtf(s), 1e-12f);
    }
    __syncthreads();
    float inv = sinv;
    for (int f = t; f < FEATN; f += 128) g_fn[row * FEATN + f] = xr[f] * inv;
}

// ---------------- 2. XW1 = X @ W1  (64x64x16 tile, 4x4 micro) ----------------
__global__ __launch_bounds__(256) void k_xw1(const float* __restrict__ X,
                                             const float* __restrict__ W1) {
    __shared__ float As[16][64];
    __shared__ float Bs[16][64];
    int tid = threadIdx.x;
    int bi = blockIdx.y * 64, bj = blockIdx.x * 64;
    int tx = tid & 15, ty = tid >> 4;
    int ar_ = tid >> 2, ac_ = (tid & 3) << 2;   // A load: row 0..63, col group
    int br_ = tid >> 4, bc_ = (tid & 15) << 2;  // B load: row 0..15, col group
    float acc[4][4];
#pragma unroll
    for (int m = 0; m < 4; m++)
#pragma unroll
        for (int n = 0; n < 4; n++) acc[m][n] = 0.f;

    for (int k0 = 0; k0 < FEATN; k0 += 16) {
        float4 a = *(const float4*)(X + (bi + ar_) * FEATN + k0 + ac_);
        As[ac_ + 0][ar_] = a.x; As[ac_ + 1][ar_] = a.y;
        As[ac_ + 2][ar_] = a.z; As[ac_ + 3][ar_] = a.w;
        float4 b = *(const float4*)(W1 + (k0 + br_) * HIDN + bj + bc_);
        *(float4*)&Bs[br_][bc_] = b;
        __syncthreads();
#pragma unroll
        for (int k = 0; k < 16; k++) {
            float av[4], bv[4];
#pragma unroll
            for (int m = 0; m < 4; m++) av[m] = As[k][ty * 4 + m];
#pragma unroll
            for (int n = 0; n < 4; n++) bv[n] = Bs[k][tx * 4 + n];
#pragma unroll
            for (int m = 0; m < 4; m++)
#pragma unroll
                for (int n = 0; n < 4; n++) acc[m][n] += av[m] * bv[n];
        }
        __syncthreads();
    }
#pragma unroll
    for (int m = 0; m < 4; m++)
#pragma unroll
        for (int n = 0; n < 4; n++)
            g_xw1[(bi + ty * 4 + m) * HIDN + bj + tx * 4 + n] = acc[m][n];
}

// ---------------- 3. sim GEMM + spatial + sigmoid epilogue ----------------
// adj = sigmoid((lam*sim + (1-lam)*exp(-d2/5000)) * temperature)
__global__ __launch_bounds__(256) void k_sim(const float* __restrict__ pos,
                                             const float* __restrict__ plam,
                                             const float* __restrict__ ptemp) {
    __shared__ float As[8][128];
    __shared__ float Bs[8][128];
    int tid = threadIdx.x;
    int bi = blockIdx.y * 128;
    int bj = blockIdx.x * 128;
    int lr = tid >> 1;
    int lc = (tid & 1) << 2;
    int tx = tid & 15, ty = tid >> 4;

    float acc[8][8];
#pragma unroll
    for (int m = 0; m < 8; m++)
#pragma unroll
        for (int n = 0; n < 8; n++) acc[m][n] = 0.f;

    const float* Abase = g_fn + (bi + lr) * FEATN + lc;
    const float* Bbase = g_fn + (bj + lr) * FEATN + lc;

    for (int k0 = 0; k0 < FEATN; k0 += 8) {
        float4 a = *(const float4*)(Abase + k0);
        float4 b = *(const float4*)(Bbase + k0);
        As[lc + 0][lr] = a.x; As[lc + 1][lr] = a.y;
        As[lc + 2][lr] = a.z; As[lc + 3][lr] = a.w;
        Bs[lc + 0][lr] = b.x; Bs[lc + 1][lr] = b.y;
        Bs[lc + 2][lr] = b.z; Bs[lc + 3][lr] = b.w;
        __syncthreads();
#pragma unroll
        for (int k = 0; k < 8; k++) {
            float ar[8], br[8];
#pragma unroll
            for (int m = 0; m < 8; m++) ar[m] = As[k][ty * 8 + m];
#pragma unroll
            for (int n = 0; n < 8; n++) br[n] = Bs[k][tx * 8 + n];
#pragma unroll
            for (int m = 0; m < 8; m++)
#pragma unroll
                for (int n = 0; n < 8; n++) acc[m][n] += ar[m] * br[n];
        }
        __syncthreads();
    }

    float lam = 1.0f / (1.0f + expf(-plam[0]));
    float T = ptemp[0];
    float oml = 1.0f - lam;

    float pix[8], piy[8], p2i[8], pjx[8], pjy[8], p2j[8];
#pragma unroll
    for (int m = 0; m < 8; m++) {
        int r = bi + ty * 8 + m;
        pix[m] = pos[2 * r]; piy[m] = pos[2 * r + 1];
        p2i[m] = pix[m] * pix[m] + piy[m] * piy[m];
    }
#pragma unroll
    for (int n = 0; n < 8; n++) {
        int c = bj + tx * 8 + n;
        pjx[n] = pos[2 * c]; pjy[n] = pos[2 * c + 1];
        p2j[n] = pjx[n] * pjx[n] + pjy[n] * pjy[n];
    }
#pragma unroll
    for (int m = 0; m < 8; m++) {
        size_t rowoff = (size_t)(bi + ty * 8 + m) * NN + bj + tx * 8;
#pragma unroll
        for (int n = 0; n < 8; n++) {
            float d2 = fmaxf(p2i[m] + p2j[n] -
                             2.0f * (pix[m] * pjx[n] + piy[m] * pjy[n]), 0.0f);
            float sp = expf(-d2 * INV2SD2);
            float raw = (lam * acc[m][n] + oml * sp) * T;
            g_adj[rowoff + n] = 1.0f / (1.0f + expf(-raw));
        }
    }
}

// ---------------- 4. row-wise exact top-20 (value desc, index asc tie-break) -----
__global__ __launch_bounds__(128) void k_topk() {
    int row = blockIdx.x, t = threadIdx.x;
    __shared__ float sv[128 * KNNN];
    __shared__ int   si[128 * KNNN];
    float* lv = sv + t * KNNN;
    int*   li = si + t * KNNN;
#pragma unroll
    for (int p = 0; p < KNNN; p++) { lv[p] = -FLT_MAX; li[p] = 0x7fffffff; }

    const float* r = g_adj + (size_t)row * NN;
    for (int j = t; j < NN; j += 128) {
        float v = r[j];
        if (v > lv[KNNN - 1]) {   // strict: equal value w/ larger index loses
            int pos = KNNN - 1;
            while (pos > 0 && v > lv[pos - 1]) {
                lv[pos] = lv[pos - 1]; li[pos] = li[pos - 1]; pos--;
            }
            lv[pos] = v; li[pos] = j;
        }
    }
    __syncthreads();

    // merge: 20 rounds of argmax over 128 sorted heads
    __shared__ float rv[4]; __shared__ int ri[4], rt[4];
    __shared__ int wt_;
    int hp = 0;
    int lane = t & 31, w = t >> 5;
    for (int it = 0; it < KNNN; it++) {
        float v  = (hp < KNNN) ? lv[hp] : -FLT_MAX;
        int   ix = (hp < KNNN) ? li[hp] : 0x7fffffff;
        int   own = t;
#pragma unroll
        for (int o = 16; o > 0; o >>= 1) {
            float v2 = __shfl_down_sync(0xffffffffu, v, o);
            int   i2 = __shfl_down_sync(0xffffffffu, ix, o);
            int   o2 = __shfl_down_sync(0xffffffffu, own, o);
            if (v2 > v || (v2 == v && i2 < ix)) { v = v2; ix = i2; own = o2; }
        }
        if (lane == 0) { rv[w] = v; ri[w] = ix; rt[w] = own; }
        __syncthreads();
        if (t == 0) {
            float bv = rv[0]; int bix = ri[0]; int bt = rt[0];
#pragma unroll
            for (int q = 1; q < 4; q++)
                if (rv[q] > bv || (rv[q] == bv && ri[q] < bix)) {
                    bv = rv[q]; bix = ri[q]; bt = rt[q];
                }
            g_val[row * KNNN + it] = bv;
            g_idx[row * KNNN + it] = bix;
            wt_ = bt;
        }
        __syncthreads();
        if (t == wt_) hp++;
        __syncthreads();
    }
}

// ---------------- 5. degrees (column sums of M = A_bin + I) ----------------
__global__ void k_deg_init() {
    int i = blockIdx.x * 256 + threadIdx.x;
    if (i < NN) g_deg[i] = 1.0f;   // identity contribution
}
__global__ void k_deg_scatter() {
    int e = blockIdx.x * 256 + threadIdx.x;
    if (e < NN * KNNN) {
        if (g_val[e] > THRF) atomicAdd(&g_deg[g_idx[e]], 1.0f);
    }
}
__global__ void k_dinv() {
    int i = blockIdx.x * 256 + threadIdx.x;
    if (i < NN) g_dinv[i] = 1.0f / sqrtf(g_deg[i]);
}

// ---------------- 6. GCN layer 1: h = relu(Mn^T (XW1) + b1) ----------------
__global__ void k_acc_init() {
    int idx = blockIdx.x * 256 + threadIdx.x;   // grid covers N*HID exactly
    int i = idx >> 8;                           // HIDN == 256
    g_acc[idx] = g_dinv[i] * g_xw1[idx];        // identity part: dinv_j * Z_j
}
__global__ __launch_bounds__(HIDN) void k_scatter1() {
    int i = blockIdx.x, f = threadIdx.x;
    __shared__ int   sj[KNNN];
    __shared__ float sw[KNNN];
    if (f < KNNN) { sj[f] = g_idx[i * KNNN + f]; sw[f] = g_val[i * KNNN + f]; }
    __syncthreads();
    float z = g_dinv[i] * g_xw1[i * HIDN + f];
#pragma unroll
    for (int k = 0; k < KNNN; k++) {
        if (sw[k] > THRF) atomicAdd(&g_acc[sj[k] * HIDN + f], z);
    }
}
__global__ void k_relu(const float* __restrict__ b1) {
    int idx = blockIdx.x * 256 + threadIdx.x;
    int i = idx >> 8, f = idx & 255;
    g_acc[idx] = fmaxf(g_dinv[i] * g_acc[idx] + b1[f], 0.0f);
}

// ---------------- 7. t1 = h @ W2 ----------------
__global__ __launch_bounds__(64) void k_hw2(const float* __restrict__ W2) {
    int i = blockIdx.x, t = threadIdx.x;
    __shared__ float sh[HIDN];
    for (int k = t; k < HIDN; k += 64) sh[k] = g_acc[i * HIDN + k];
    __syncthreads();
    if (t < KMN) {
        float s = 0.f;
#pragma unroll 8
        for (int k = 0; k < HIDN; k++) s += sh[k] * W2[k * KMN + t];
        g_t1[i * KMN + t] = s;
    }
}

// ---------------- 8. GCN layer 2 + softmax -> S ----------------
__global__ __launch_bounds__(64) void k_sacc_init() {
    int i = blockIdx.x, t = threadIdx.x;
    if (t < KMN) g_sacc[i * KMN + t] = g_dinv[i] * g_t1[i * KMN + t];
}
__global__ __launch_bounds__(64) void k_scatter2() {
    int i = blockIdx.x, t = threadIdx.x;
    __shared__ int   sj[KNNN];
    __shared__ float sw[KNNN];
    if (t < KNNN) { sj[t] = g_idx[i * KNNN + t]; sw[t] = g_val[i * KNNN + t]; }
    __syncthreads();
    if (t < KMN) {
        float z = g_dinv[i] * g_t1[i * KMN + t];
#pragma unroll
        for (int k = 0; k < KNNN; k++) {
            if (sw[k] > THRF) atomicAdd(&g_sacc[sj[k] * KMN + t], z);
        }
    }
}
__global__ __launch_bounds__(64) void k_softmax(const float* __restrict__ b2,
                                                float* __restrict__ S) {
    int i = blockIdx.x, t = threadIdx.x;
    __shared__ float red[64];
    float v = (t < KMN) ? g_dinv[i] * g_sacc[i * KMN + t] + b2[t] : -FLT_MAX;
    red[t] = v;
#pragma unroll
    for (int o = 32; o > 0; o >>= 1) {
        __syncthreads();
        if (t < o) red[t] = fmaxf(red[t], red[t + o]);
    }
    __syncthreads();
    float mx = red[0];
    __syncthreads();
    float e = (t < KMN) ? expf(v - mx) : 0.f;
    red[t] = e;
#pragma unroll
    for (int o = 32; o > 0; o >>= 1) {
        __syncthreads();
        if (t < o) red[t] += red[t + o];
    }
    __syncthreads();
    float inv = 1.0f / red[0];
    if (t < KMN) S[i * KMN + t] = e * inv;
}

// ---------------- 9. t2 = adj @ S (sparse, uses full masked adj values) -----
__global__ __launch_bounds__(64) void k_adjS(const float* __restrict__ S) {
    int i = blockIdx.x, t = threadIdx.x;
    __shared__ int   sj[KNNN];
    __shared__ float sw[KNNN];
    if (t < KNNN) { sj[t] = g_idx[i * KNNN + t]; sw[t] = g_val[i * KNNN + t]; }
    __syncthreads();
    if (t < KMN) {
        float a = 0.f;
#pragma unroll
        for (int k = 0; k < KNNN; k++) a += sw[k] * S[sj[k] * KMN + t];
        g_t2[i * KMN + t] = a;
    }
}

// ---------------- 10. A_coarse = S^T @ t2 (partial per 128-row block) -------
__global__ __launch_bounds__(256) void k_Ac(const float* __restrict__ S) {
    int t = threadIdx.x;
    int r0 = blockIdx.x * 128;
    __shared__ float sS[KMN], sT[KMN];
    float acc[10];
    int c1[10], c2[10]; bool ok[10];
#pragma unroll
    for (int p = 0; p < 10; p++) {
        int e = t + p * 256;
        ok[p] = (e < KMN * KMN);
        c1[p] = ok[p] ? e / KMN : 0;
        c2[p] = ok[p] ? e % KMN : 0;
        acc[p] = 0.f;
    }
    for (int r = 0; r < 128; r++) {
        int i = r0 + r;
        if (t < KMN) sS[t] = S[i * KMN + t];
        else if (t >= 64 && t < 64 + KMN) sT[t - 64] = g_t2[i * KMN + t - 64];
        __syncthreads();
#pragma unroll
        for (int p = 0; p < 10; p++)
            if (ok[p]) acc[p] += sS[c1[p]] * sT[c2[p]];
        __syncthreads();
    }
#pragma unroll
    for (int p = 0; p < 10; p++)
        if (ok[p]) atomicAdd(&g_Ac[t + p * 256], acc[p]);
}

// ---------------- 11. X_t = S^T @ X (partials, 128-row x 128-feat blocks) ---
__global__ __launch_bounds__(256) void k_Xt(const float* __restrict__ X,
                                            const float* __restrict__ S,
                                            float* __restrict__ outXt) {
    int t = threadIdx.x;
    int fc = blockIdx.x * 128;
    int r0 = blockIdx.y * 128;
    int f = t & 127, ch = t >> 7;      // ch in {0,1}, clusters [ch*25, ch*25+25)
    __shared__ float sS[KMN];
    __shared__ float sX[128];
    float acc[25];
#pragma unroll
    for (int c = 0; c < 25; c++) acc[c] = 0.f;
    for (int r = 0; r < 128; r++) {
        int i = r0 + r;
        if (t < KMN) sS[t] = S[i * KMN + t];
        if (t >= 128) sX[t - 128] = X[i * FEATN + fc + t - 128];
        __syncthreads();
        float xv = sX[f];
#pragma unroll
        for (int c = 0; c < 25; c++) acc[c] += sS[ch * 25 + c] * xv;
        __syncthreads();
    }
#pragma unroll
    for (int c = 0; c < 25; c++)
        atomicAdd(&outXt[(ch * 25 + c) * FEATN + fc + f], acc[c]);
}

// ---------------- 12. spatial loss: sum over bin edges (S_i.S_j)*d2 ---------
__global__ __launch_bounds__(256) void k_loss(const float* __restrict__ S,
                                              const float* __restrict__ pos) {
    int warp = (blockIdx.x * 256 + threadIdx.x) >> 5;
    int lane = threadIdx.x & 31;
    if (warp >= NN) return;
    int i = warp;
    float s0 = (lane < KMN) ? S[i * KMN + lane] : 0.f;
    bool has2 = (lane + 32 < KMN);
    float s1 = has2 ? S[i * KMN + lane + 32] : 0.f;
    float xi = pos[2 * i], yi = pos[2 * i + 1];
    float p2i = xi * xi + yi * yi;
    float lsum = 0.f; int cnt = 0;
#pragma unroll
    for (int k = 0; k < KNNN; k++) {
        float v = g_val[i * KNNN + k];
        if (v > THRF) {
            int j = g_idx[i * KNNN + k];
            float xj = pos[2 * j], yj = pos[2 * j + 1];
            float d2 = fmaxf(p2i + xj * xj + yj * yj -
                             2.0f * (xi * xj + yi * yj), 0.0f);
            float dp = s0 * ((lane < KMN) ? S[j * KMN + lane] : 0.f);
            if (has2) dp += s1 * S[j * KMN + lane + 32];
            lsum += d2 * dp;
            cnt++;
        }
    }
#pragma unroll
    for (int o = 16; o > 0; o >>= 1) lsum += __shfl_down_sync(0xffffffffu, lsum, o);
    if (lane == 0) {
        atomicAdd(&g_loss, lsum);
        atomicAdd(&g_E, (float)cnt);
    }
}

// ---------------- zero/init + finalize ----------------
__global__ void k_zero(float* __restrict__ outXt) {
    int idx = blockIdx.x * 256 + threadIdx.x;
    if (idx < KMN * FEATN) outXt[idx] = 0.f;
    if (idx < KMN * KMN) g_Ac[idx] = 0.f;
    if (idx == 0) { g_loss = 0.f; g_E = 0.f; }
}
__global__ void k_final(const float* __restrict__ psw,
                        const float* __restrict__ plam,
                        float* __restrict__ out) {
    int idx = blockIdx.x * 256 + threadIdx.x;
    const int offA = NN * KMN + KMN * FEATN;
    if (idx < KMN * KMN) {
        float a = g_Ac[idx];
        out[offA + idx] = (a > THRF) ? a : 0.f;
    }
    if (idx == 0) {
        out[offA + KMN * KMN] = psw[0] * g_loss / g_E;
        out[offA + KMN * KMN + 1] = 1.0f / (1.0f + expf(-plam[0]));
    }
}

// ---------------- launcher ----------------
extern "C" void kernel_launch(void* const* d_in, const int* in_sizes, int n_in,
                              void* d_out, int out_size) {
    const float* X    = (const float*)d_in[0];
    const float* pos  = (const float*)d_in[1];
    const float* lamw = (const float*)d_in[2];
    const float* temp = (const float*)d_in[3];
    const float* sw   = (const float*)d_in[4];
    const float* W1   = (const float*)d_in[5];
    const float* b1   = (const float*)d_in[6];
    const float* W2   = (const float*)d_in[7];
    const float* b2   = (const float*)d_in[8];
    float* out  = (float*)d_out;
    float* S    = out;              // [N, K]
    float* oXt  = out + NN * KMN;   // [K, FEAT]

    k_prep<<<NN, 128>>>(X);
    k_xw1<<<dim3(HIDN / 64, NN / 64), 256>>>(X, W1);
    k_sim<<<dim3(NN / 128, NN / 128), 256>>>(pos, lamw, temp);
    k_topk<<<NN, 128>>>();
    k_zero<<<(KMN * FEATN + 255) / 256, 256>>>(oXt);
    k_deg_init<<<NN / 256, 256>>>();
    k_deg_scatter<<<(NN * KNNN + 255) / 256, 256>>>();
    k_dinv<<<NN / 256, 256>>>();
    k_acc_init<<<(NN * HIDN) / 256, 256>>>();
    k_scatter1<<<NN, HIDN>>>();
    k_relu<<<(NN * HIDN) / 256, 256>>>(b1);
    k_hw2<<<NN, 64>>>(W2);
    k_sacc_init<<<NN, 64>>>();
    k_scatter2<<<NN, 64>>>();
    k_softmax<<<NN, 64>>>(b2, S);
    k_adjS<<<NN, 64>>>(S);
    k_Ac<<<NN / 128, 256>>>(S);
    k_Xt<<<dim3(FEATN / 128, NN / 128), 256>>>(X, S, oXt);
    k_loss<<<NN / 8, 256>>>(S, pos);
    k_final<<<(KMN * KMN + 255) / 256, 256>>>(sw, lamw, out);
}

// round 7
// speedup vs baseline: 1.6881x; 1.6881x over previous
#include <cuda_runtime.h>
#include <math.h>
#include <float.h>

// Problem constants
#define NN    6144
#define FEATN 512
#define HIDN  256
#define KMN   50
#define KNNN  20
#define THRF  0.1f
// spatial: exp(-d2 / (2*50^2)) = exp(-d2/5000)
#define INV2SD2 (1.0f/5000.0f)
#define CAPC  128

// ---------------- device scratch (static; no allocation allowed) ----------------
__device__ float g_fn[NN * FEATN];                 // normalized features
__device__ float g_adj[(size_t)NN * NN];           // dense RAW scores (pre-sigmoid)
__device__ float g_xw1[NN * HIDN];                 // X @ W1
__device__ float g_acc[NN * HIDN];                 // GCN1 accumulator -> h
__device__ float g_t1[NN * KMN];                   // h @ W2
__device__ float g_sacc[NN * KMN];                 // GCN2 accumulator
__device__ float g_t2[NN * KMN];                   // adj @ S
__device__ float g_deg[NN];
__device__ float g_dinv[NN];
__device__ int   g_idx[NN * KNNN];
__device__ float g_val[NN * KNNN];                 // sigmoid(adj) of selected top-20
__device__ float g_Ac[KMN * KMN];
__device__ float g_loss;
__device__ float g_E;

// ---------------- 1. normalize rows of features ----------------
__global__ __launch_bounds__(128) void k_prep(const float* __restrict__ X) {
    int row = blockIdx.x, t = threadIdx.x;
    const float* xr = X + row * FEATN;
    float ss = 0.f;
    for (int f = t; f < FEATN; f += 128) { float v = xr[f]; ss += v * v; }
    for (int o = 16; o > 0; o >>= 1) ss += __shfl_down_sync(0xffffffffu, ss, o);
    __shared__ float red[4];
    __shared__ float sinv;
    if ((t & 31) == 0) red[t >> 5] = ss;
    __syncthreads();
    if (t == 0) {
        float s = red[0] + red[1] + red[2] + red[3];
        sinv = 1.0f / fmaxf(sqrtf(s), 1e-12f);
    }
    __syncthreads();
    float inv = sinv;
    for (int f = t; f < FEATN; f += 128) g_fn[row * FEATN + f] = xr[f] * inv;
}

// ---------------- 2. XW1 = X @ W1  (64x64x16 tile, 4x4 micro) ----------------
__global__ __launch_bounds__(256) void k_xw1(const float* __restrict__ X,
                                             const float* __restrict__ W1) {
    __shared__ float As[16][64];
    __shared__ float Bs[16][64];
    int tid = threadIdx.x;
    int bi = blockIdx.y * 64, bj = blockIdx.x * 64;
    int tx = tid & 15, ty = tid >> 4;
    int ar_ = tid >> 2, ac_ = (tid & 3) << 2;
    int br_ = tid >> 4, bc_ = (tid & 15) << 2;
    float acc[4][4];
#pragma unroll
    for (int m = 0; m < 4; m++)
#pragma unroll
        for (int n = 0; n < 4; n++) acc[m][n] = 0.f;

    for (int k0 = 0; k0 < FEATN; k0 += 16) {
        float4 a = *(const float4*)(X + (bi + ar_) * FEATN + k0 + ac_);
        As[ac_ + 0][ar_] = a.x; As[ac_ + 1][ar_] = a.y;
        As[ac_ + 2][ar_] = a.z; As[ac_ + 3][ar_] = a.w;
        float4 b = *(const float4*)(W1 + (k0 + br_) * HIDN + bj + bc_);
        *(float4*)&Bs[br_][bc_] = b;
        __syncthreads();
#pragma unroll
        for (int k = 0; k < 16; k++) {
            float av[4], bv[4];
#pragma unroll
            for (int m = 0; m < 4; m++) av[m] = As[k][ty * 4 + m];
#pragma unroll
            for (int n = 0; n < 4; n++) bv[n] = Bs[k][tx * 4 + n];
#pragma unroll
            for (int m = 0; m < 4; m++)
#pragma unroll
                for (int n = 0; n < 4; n++) acc[m][n] += av[m] * bv[n];
        }
        __syncthreads();
    }
#pragma unroll
    for (int m = 0; m < 4; m++)
#pragma unroll
        for (int n = 0; n < 4; n++)
            g_xw1[(bi + ty * 4 + m) * HIDN + bj + tx * 4 + n] = acc[m][n];
}

// ---------------- 3. sim GEMM + spatial epilogue (store RAW score) ----------------
// raw = (lam*sim + (1-lam)*exp(-d2/5000)) * temperature   (sigmoid deferred)
__global__ __launch_bounds__(256) void k_sim(const float* __restrict__ pos,
                                             const float* __restrict__ plam,
                                             const float* __restrict__ ptemp) {
    __shared__ float As[8][128];
    __shared__ float Bs[8][128];
    int tid = threadIdx.x;
    int bi = blockIdx.y * 128;
    int bj = blockIdx.x * 128;
    int lr = tid >> 1;
    int lc = (tid & 1) << 2;
    int tx = tid & 15, ty = tid >> 4;

    float acc[8][8];
#pragma unroll
    for (int m = 0; m < 8; m++)
#pragma unroll
        for (int n = 0; n < 8; n++) acc[m][n] = 0.f;

    const float* Abase = g_fn + (bi + lr) * FEATN + lc;
    const float* Bbase = g_fn + (bj + lr) * FEATN + lc;

    for (int k0 = 0; k0 < FEATN; k0 += 8) {
        float4 a = *(const float4*)(Abase + k0);
        float4 b = *(const float4*)(Bbase + k0);
        As[lc + 0][lr] = a.x; As[lc + 1][lr] = a.y;
        As[lc + 2][lr] = a.z; As[lc + 3][lr] = a.w;
        Bs[lc + 0][lr] = b.x; Bs[lc + 1][lr] = b.y;
        Bs[lc + 2][lr] = b.z; Bs[lc + 3][lr] = b.w;
        __syncthreads();
#pragma unroll
        for (int k = 0; k < 8; k++) {
            float ar[8], br[8];
#pragma unroll
            for (int m = 0; m < 8; m++) ar[m] = As[k][ty * 8 + m];
#pragma unroll
            for (int n = 0; n < 8; n++) br[n] = Bs[k][tx * 8 + n];
#pragma unroll
            for (int m = 0; m < 8; m++)
#pragma unroll
                for (int n = 0; n < 8; n++) acc[m][n] += ar[m] * br[n];
        }
        __syncthreads();
    }

    float lam = 1.0f / (1.0f + expf(-plam[0]));
    float T = ptemp[0];
    float oml = 1.0f - lam;

    float pix[8], piy[8], p2i[8], pjx[8], pjy[8], p2j[8];
#pragma unroll
    for (int m = 0; m < 8; m++) {
        int r = bi + ty * 8 + m;
        pix[m] = pos[2 * r]; piy[m] = pos[2 * r + 1];
        p2i[m] = pix[m] * pix[m] + piy[m] * piy[m];
    }
#pragma unroll
    for (int n = 0; n < 8; n++) {
        int c = bj + tx * 8 + n;
        pjx[n] = pos[2 * c]; pjy[n] = pos[2 * c + 1];
        p2j[n] = pjx[n] * pjx[n] + pjy[n] * pjy[n];
    }
#pragma unroll
    for (int m = 0; m < 8; m++) {
        size_t rowoff = (size_t)(bi + ty * 8 + m) * NN + bj + tx * 8;
#pragma unroll
        for (int n = 0; n < 8; n++) {
            float d2 = fmaxf(p2i[m] + p2j[n] -
                             2.0f * (pix[m] * pjx[n] + piy[m] * pjy[n]), 0.0f);
            float sp = __expf(-d2 * INV2SD2);
            g_adj[rowoff + n] = (lam * acc[m][n] + oml * sp) * T;
        }
    }
}

// ---------------- 4. row-wise exact top-20 via register binary-search select -----
// keys: monotone u32 mapping of float (value desc, tie -> smaller index wins)
__global__ __launch_bounds__(128) void k_topk() {
    int row = blockIdx.x, t = threadIdx.x;
    const float* r = g_adj + (size_t)row * NN;

    unsigned key[48];
#pragma unroll
    for (int k = 0; k < 48; k++) {
        unsigned b = __float_as_uint(r[t + k * 128]);
        key[k] = (b & 0x80000000u) ? ~b : (b | 0x80000000u);
    }

    __shared__ int scnt[4];
    __shared__ unsigned smm[8];

    // per-row min/max of keys to seed the search range
    unsigned kmin = key[0], kmax = key[0];
#pragma unroll
    for (int k = 1; k < 48; k++) {
        kmin = min(kmin, key[k]);
        kmax = max(kmax, key[k]);
    }
    for (int o = 16; o > 0; o >>= 1) {
        kmin = min(kmin, __shfl_down_sync(0xffffffffu, kmin, o));
        kmax = max(kmax, __shfl_down_sync(0xffffffffu, kmax, o));
    }
    if ((t & 31) == 0) { smm[t >> 5] = kmin; smm[4 + (t >> 5)] = kmax; }
    __syncthreads();
    unsigned lo = min(min(smm[0], smm[1]), min(smm[2], smm[3]));
    unsigned hi = max(max(smm[4], smm[5]), max(smm[6], smm[7]));
    if (hi != 0xffffffffu) hi += 1;   // exclusive upper bound
    __syncthreads();

    // binary search: invariant count(key >= lo) >= 20
    for (int it = 0; it < 34; it++) {
        if (hi - lo <= 1) break;
        unsigned mid = lo + ((hi - lo) >> 1);
        int c = 0;
#pragma unroll
        for (int k = 0; k < 48; k++) c += (key[k] >= mid) ? 1 : 0;
        for (int o = 16; o > 0; o >>= 1) c += __shfl_down_sync(0xffffffffu, c, o);
        if ((t & 31) == 0) scnt[t >> 5] = c;
        __syncthreads();
        int tot = scnt[0] + scnt[1] + scnt[2] + scnt[3];
        __syncthreads();
        if (tot >= 20) {
            lo = mid;
            if (tot <= 96) break;     // small enough candidate set
        } else {
            hi = mid;
        }
    }

    // gather candidates >= lo (packed key|~idx for exact tie ordering)
    __shared__ unsigned long long cand[CAPC];
    __shared__ int cnum;
    cand[t] = 0ull;
    if (t == 0) cnum = 0;
    __syncthreads();
#pragma unroll
    for (int k = 0; k < 48; k++) {
        if (key[k] >= lo) {
            int p = atomicAdd(&cnum, 1);
            if (p < CAPC)
                cand[p] = ((unsigned long long)key[k] << 32) |
                          (unsigned)(~(t + k * 128));
        }
    }
    __syncthreads();

    // warp 0: 20 rounds of argmax over candidates
    if (t < 32) {
        for (int it = 0; it < KNNN; it++) {
            unsigned long long best = 0ull;
            int bslot = 0;
#pragma unroll
            for (int s = 0; s < CAPC / 32; s++) {
                unsigned long long c = cand[t + s * 32];
                if (c > best) { best = c; bslot = t + s * 32; }
            }
#pragma unroll
            for (int o = 16; o > 0; o >>= 1) {
                unsigned long long b2 = __shfl_down_sync(0xffffffffu, best, o);
                int s2 = __shfl_down_sync(0xffffffffu, bslot, o);
                if (b2 > best) { best = b2; bslot = s2; }
            }
            bslot = __shfl_sync(0xffffffffu, bslot, 0);
            if (t == 0) {
                unsigned kk = (unsigned)(best >> 32);
                unsigned fb = (kk & 0x80000000u) ? (kk & 0x7fffffffu) : ~kk;
                float raw = __uint_as_float(fb);
                g_val[row * KNNN + it] = 1.0f / (1.0f + expf(-raw));
                g_idx[row * KNNN + it] = (int)(~(unsigned)(best & 0xffffffffu));
                cand[bslot] = 0ull;
            }
            __syncwarp();
        }
    }
}

// ---------------- 5. degrees (column sums of M = A_bin + I) ----------------
__global__ void k_deg_init() {
    int i = blockIdx.x * 256 + threadIdx.x;
    if (i < NN) g_deg[i] = 1.0f;
}
__global__ void k_deg_scatter() {
    int e = blockIdx.x * 256 + threadIdx.x;
    if (e < NN * KNNN) {
        if (g_val[e] > THRF) atomicAdd(&g_deg[g_idx[e]], 1.0f);
    }
}
__global__ void k_dinv() {
    int i = blockIdx.x * 256 + threadIdx.x;
    if (i < NN) g_dinv[i] = 1.0f / sqrtf(g_deg[i]);
}

// ---------------- 6. GCN layer 1: h = relu(Mn^T (XW1) + b1) ----------------
__global__ void k_acc_init() {
    int idx = blockIdx.x * 256 + threadIdx.x;
    int i = idx >> 8;
    g_acc[idx] = g_dinv[i] * g_xw1[idx];
}
__global__ __launch_bounds__(HIDN) void k_scatter1() {
    int i = blockIdx.x, f = threadIdx.x;
    __shared__ int   sj[KNNN];
    __shared__ float sw[KNNN];
    if (f < KNNN) { sj[f] = g_idx[i * KNNN + f]; sw[f] = g_val[i * KNNN + f]; }
    __syncthreads();
    float z = g_dinv[i] * g_xw1[i * HIDN + f];
#pragma unroll
    for (int k = 0; k < KNNN; k++) {
        if (sw[k] > THRF) atomicAdd(&g_acc[sj[k] * HIDN + f], z);
    }
}
__global__ void k_relu(const float* __restrict__ b1) {
    int idx = blockIdx.x * 256 + threadIdx.x;
    int i = idx >> 8, f = idx & 255;
    g_acc[idx] = fmaxf(g_dinv[i] * g_acc[idx] + b1[f], 0.0f);
}

// ---------------- 7. t1 = h @ W2 ----------------
__global__ __launch_bounds__(64) void k_hw2(const float* __restrict__ W2) {
    int i = blockIdx.x, t = threadIdx.x;
    __shared__ float sh[HIDN];
    for (int k = t; k < HIDN; k += 64) sh[k] = g_acc[i * HIDN + k];
    __syncthreads();
    if (t < KMN) {
        float s = 0.f;
#pragma unroll 8
        for (int k = 0; k < HIDN; k++) s += sh[k] * W2[k * KMN + t];
        g_t1[i * KMN + t] = s;
    }
}

// ---------------- 8. GCN layer 2 + softmax -> S ----------------
__global__ __launch_bounds__(64) void k_sacc_init() {
    int i = blockIdx.x, t = threadIdx.x;
    if (t < KMN) g_sacc[i * KMN + t] = g_dinv[i] * g_t1[i * KMN + t];
}
__global__ __launch_bounds__(64) void k_scatter2() {
    int i = blockIdx.x, t = threadIdx.x;
    __shared__ int   sj[KNNN];
    __shared__ float sw[KNNN];
    if (t < KNNN) { sj[t] = g_idx[i * KNNN + t]; sw[t] = g_val[i * KNNN + t]; }
    __syncthreads();
    if (t < KMN) {
        float z = g_dinv[i] * g_t1[i * KMN + t];
#pragma unroll
        for (int k = 0; k < KNNN; k++) {
            if (sw[k] > THRF) atomicAdd(&g_sacc[sj[k] * KMN + t], z);
        }
    }
}
__global__ __launch_bounds__(64) void k_softmax(const float* __restrict__ b2,
                                                float* __restrict__ S) {
    int i = blockIdx.x, t = threadIdx.x;
    __shared__ float red[64];
    float v = (t < KMN) ? g_dinv[i] * g_sacc[i * KMN + t] + b2[t] : -FLT_MAX;
    red[t] = v;
#pragma unroll
    for (int o = 32; o > 0; o >>= 1) {
        __syncthreads();
        if (t < o) red[t] = fmaxf(red[t], red[t + o]);
    }
    __syncthreads();
    float mx = red[0];
    __syncthreads();
    float e = (t < KMN) ? expf(v - mx) : 0.f;
    red[t] = e;
#pragma unroll
    for (int o = 32; o > 0; o >>= 1) {
        __syncthreads();
        if (t < o) red[t] += red[t + o];
    }
    __syncthreads();
    float inv = 1.0f / red[0];
    if (t < KMN) S[i * KMN + t] = e * inv;
}

// ---------------- 9. t2 = adj @ S (sparse, masked adj values) -----
__global__ __launch_bounds__(64) void k_adjS(const float* __restrict__ S) {
    int i = blockIdx.x, t = threadIdx.x;
    __shared__ int   sj[KNNN];
    __shared__ float sw[KNNN];
    if (t < KNNN) { sj[t] = g_idx[i * KNNN + t]; sw[t] = g_val[i * KNNN + t]; }
    __syncthreads();
    if (t < KMN) {
        float a = 0.f;
#pragma unroll
        for (int k = 0; k < KNNN; k++) a += sw[k] * S[sj[k] * KMN + t];
        g_t2[i * KMN + t] = a;
    }
}

// ---------------- 10. A_coarse = S^T @ t2 (partial per 128-row block) -------
__global__ __launch_bounds__(256) void k_Ac(const float* __restrict__ S) {
    int t = threadIdx.x;
    int r0 = blockIdx.x * 128;
    __shared__ float sS[KMN], sT[KMN];
    float acc[10];
    int c1[10], c2[10]; bool ok[10];
#pragma unroll
    for (int p = 0; p < 10; p++) {
        int e = t + p * 256;
        ok[p] = (e < KMN * KMN);
        c1[p] = ok[p] ? e / KMN : 0;
        c2[p] = ok[p] ? e % KMN : 0;
        acc[p] = 0.f;
    }
    for (int r = 0; r < 128; r++) {
        int i = r0 + r;
        if (t < KMN) sS[t] = S[i * KMN + t];
        else if (t >= 64 && t < 64 + KMN) sT[t - 64] = g_t2[i * KMN + t - 64];
        __syncthreads();
#pragma unroll
        for (int p = 0; p < 10; p++)
            if (ok[p]) acc[p] += sS[c1[p]] * sT[c2[p]];
        __syncthreads();
    }
#pragma unroll
    for (int p = 0; p < 10; p++)
        if (ok[p]) atomicAdd(&g_Ac[t + p * 256], acc[p]);
}

// ---------------- 11. X_t = S^T @ X (partials, 128-row x 128-feat blocks) ---
__global__ __launch_bounds__(256) void k_Xt(const float* __restrict__ X,
                                            const float* __restrict__ S,
                                            float* __restrict__ outXt) {
    int t = threadIdx.x;
    int fc = blockIdx.x * 128;
    int r0 = blockIdx.y * 128;
    int f = t & 127, ch = t >> 7;
    __shared__ float sS[KMN];
    __shared__ float sX[128];
    float acc[25];
#pragma unroll
    for (int c = 0; c < 25; c++) acc[c] = 0.f;
    for (int r = 0; r < 128; r++) {
        int i = r0 + r;
        if (t < KMN) sS[t] = S[i * KMN + t];
        if (t >= 128) sX[t - 128] = X[i * FEATN + fc + t - 128];
        __syncthreads();
        float xv = sX[f];
#pragma unroll
        for (int c = 0; c < 25; c++) acc[c] += sS[ch * 25 + c] * xv;
        __syncthreads();
    }
#pragma unroll
    for (int c = 0; c < 25; c++)
        atomicAdd(&outXt[(ch * 25 + c) * FEATN + fc + f], acc[c]);
}

// ---------------- 12. spatial loss: sum over bin edges (S_i.S_j)*d2 ---------
__global__ __launch_bounds__(256) void k_loss(const float* __restrict__ S,
                                              const float* __restrict__ pos) {
    int warp = (blockIdx.x * 256 + threadIdx.x) >> 5;
    int lane = threadIdx.x & 31;
    if (warp >= NN) return;
    int i = warp;
    float s0 = (lane < KMN) ? S[i * KMN + lane] : 0.f;
    bool has2 = (lane + 32 < KMN);
    float s1 = has2 ? S[i * KMN + lane + 32] : 0.f;
    float xi = pos[2 * i], yi = pos[2 * i + 1];
    float p2i = xi * xi + yi * yi;
    float lsum = 0.f; int cnt = 0;
#pragma unroll
    for (int k = 0; k < KNNN; k++) {
        float v = g_val[i * KNNN + k];
        if (v > THRF) {
            int j = g_idx[i * KNNN + k];
            float xj = pos[2 * j], yj = pos[2 * j + 1];
            float d2 = fmaxf(p2i + xj * xj + yj * yj -
                             2.0f * (xi * xj + yi * yj), 0.0f);
            float dp = s0 * ((lane < KMN) ? S[j * KMN + lane] : 0.f);
            if (has2) dp += s1 * S[j * KMN + lane + 32];
            lsum += d2 * dp;
            cnt++;
        }
    }
#pragma unroll
    for (int o = 16; o > 0; o >>= 1) lsum += __shfl_down_sync(0xffffffffu, lsum, o);
    if (lane == 0) {
        atomicAdd(&g_loss, lsum);
        atomicAdd(&g_E, (float)cnt);
    }
}

// ---------------- zero/init + finalize ----------------
__global__ void k_zero(float* __restrict__ outXt) {
    int idx = blockIdx.x * 256 + threadIdx.x;
    if (idx < KMN * FEATN) outXt[idx] = 0.f;
    if (idx < KMN * KMN) g_Ac[idx] = 0.f;
    if (idx == 0) { g_loss = 0.f; g_E = 0.f; }
}
__global__ void k_final(const float* __restrict__ psw,
                        const float* __restrict__ plam,
                        float* __restrict__ out) {
    int idx = blockIdx.x * 256 + threadIdx.x;
    const int offA = NN * KMN + KMN * FEATN;
    if (idx < KMN * KMN) {
        float a = g_Ac[idx];
        out[offA + idx] = (a > THRF) ? a : 0.f;
    }
    if (idx == 0) {
        out[offA + KMN * KMN] = psw[0] * g_loss / g_E;
        out[offA + KMN * KMN + 1] = 1.0f / (1.0f + expf(-plam[0]));
    }
}

// ---------------- launcher ----------------
extern "C" void kernel_launch(void* const* d_in, const int* in_sizes, int n_in,
                              void* d_out, int out_size) {
    const float* X    = (const float*)d_in[0];
    const float* pos  = (const float*)d_in[1];
    const float* lamw = (const float*)d_in[2];
    const float* temp = (const float*)d_in[3];
    const float* sw   = (const float*)d_in[4];
    const float* W1   = (const float*)d_in[5];
    const float* b1   = (const float*)d_in[6];
    const float* W2   = (const float*)d_in[7];
    const float* b2   = (const float*)d_in[8];
    float* out  = (float*)d_out;
    float* S    = out;              // [N, K]
    float* oXt  = out + NN * KMN;   // [K, FEAT]

    k_prep<<<NN, 128>>>(X);
    k_xw1<<<dim3(HIDN / 64, NN / 64), 256>>>(X, W1);
    k_sim<<<dim3(NN / 128, NN / 128), 256>>>(pos, lamw, temp);
    k_topk<<<NN, 128>>>();
    k_zero<<<(KMN * FEATN + 255) / 256, 256>>>(oXt);
    k_deg_init<<<NN / 256, 256>>>();
    k_deg_scatter<<<(NN * KNNN + 255) / 256, 256>>>();
    k_dinv<<<NN / 256, 256>>>();
    k_acc_init<<<(NN * HIDN) / 256, 256>>>();
    k_scatter1<<<NN, HIDN>>>();
    k_relu<<<(NN * HIDN) / 256, 256>>>(b1);
    k_hw2<<<NN, 64>>>(W2);
    k_sacc_init<<<NN, 64>>>();
    k_scatter2<<<NN, 64>>>();
    k_softmax<<<NN, 64>>>(b2, S);
    k_adjS<<<NN, 64>>>(S);
    k_Ac<<<NN / 128, 256>>>(S);
    k_Xt<<<dim3(FEATN / 128, NN / 128), 256>>>(X, S, oXt);
    k_loss<<<NN / 8, 256>>>(S, pos);
    k_final<<<(KMN * KMN + 255) / 256, 256>>>(sw, lamw, out);
}

// round 8
// speedup vs baseline: 1.6897x; 1.0009x over previous
#include <cuda_runtime.h>
#include <math.h>
#include <float.h>

// Problem constants
#define NN    6144
#define FEATN 512
#define HIDN  256
#define KMN   50
#define KNNN  20
#define THRF  0.1f
// spatial: exp(-d2 / (2*50^2)) = exp(-d2/5000)
#define INV2SD2 (1.0f/5000.0f)
#define CAPC  128

// ---------------- device scratch (static; no allocation allowed) ----------------
__device__ float g_fn[NN * FEATN];                 // normalized features
__device__ float g_adj[(size_t)NN * NN];           // dense RAW scores (pre-sigmoid)
__device__ float g_xw1[NN * HIDN];                 // X @ W1
__device__ float g_acc[NN * HIDN];                 // GCN1 accumulator -> h
__device__ float g_t1[NN * KMN];                   // h @ W2
__device__ float g_sacc[NN * KMN];                 // GCN2 accumulator
__device__ float g_t2[NN * KMN];                   // adj @ S
__device__ float g_deg[NN];
__device__ float g_dinv[NN];
__device__ int   g_idx[NN * KNNN];
__device__ float g_val[NN * KNNN];                 // sigmoid(adj) of selected top-20
__device__ float g_Ac[KMN * KMN];
__device__ float g_loss;
__device__ float g_E;

// ---------------- 1. normalize rows of features ----------------
__global__ __launch_bounds__(128) void k_prep(const float* __restrict__ X) {
    int row = blockIdx.x, t = threadIdx.x;
    const float* xr = X + row * FEATN;
    float ss = 0.f;
    for (int f = t; f < FEATN; f += 128) { float v = xr[f]; ss += v * v; }
    for (int o = 16; o > 0; o >>= 1) ss += __shfl_down_sync(0xffffffffu, ss, o);
    __shared__ float red[4];
    __shared__ float sinv;
    if ((t & 31) == 0) red[t >> 5] = ss;
    __syncthreads();
    if (t == 0) {
        float s = red[0] + red[1] + red[2] + red[3];
        sinv = 1.0f / fmaxf(sqrtf(s), 1e-12f);
    }
    __syncthreads();
    float inv = sinv;
    for (int f = t; f < FEATN; f += 128) g_fn[row * FEATN + f] = xr[f] * inv;
}

// ---------------- 2. XW1 = X @ W1  (64x64x16 tile, 4x4 micro) ----------------
__global__ __launch_bounds__(256) void k_xw1(const float* __restrict__ X,
                                             const float* __restrict__ W1) {
    __shared__ float As[16][64];
    __shared__ float Bs[16][64];
    int tid = threadIdx.x;
    int bi = blockIdx.y * 64, bj = blockIdx.x * 64;
    int tx = tid & 15, ty = tid >> 4;
    int ar_ = tid >> 2, ac_ = (tid & 3) << 2;
    int br_ = tid >> 4, bc_ = (tid & 15) << 2;
    float acc[4][4];
#pragma unroll
    for (int m = 0; m < 4; m++)
#pragma unroll
        for (int n = 0; n < 4; n++) acc[m][n] = 0.f;

    for (int k0 = 0; k0 < FEATN; k0 += 16) {
        float4 a = *(const float4*)(X + (bi + ar_) * FEATN + k0 + ac_);
        As[ac_ + 0][ar_] = a.x; As[ac_ + 1][ar_] = a.y;
        As[ac_ + 2][ar_] = a.z; As[ac_ + 3][ar_] = a.w;
        float4 b = *(const float4*)(W1 + (k0 + br_) * HIDN + bj + bc_);
        *(float4*)&Bs[br_][bc_] = b;
        __syncthreads();
#pragma unroll
        for (int k = 0; k < 16; k++) {
            float av[4], bv[4];
#pragma unroll
            for (int m = 0; m < 4; m++) av[m] = As[k][ty * 4 + m];
#pragma unroll
            for (int n = 0; n < 4; n++) bv[n] = Bs[k][tx * 4 + n];
#pragma unroll
            for (int m = 0; m < 4; m++)
#pragma unroll
                for (int n = 0; n < 4; n++) acc[m][n] += av[m] * bv[n];
        }
        __syncthreads();
    }
#pragma unroll
    for (int m = 0; m < 4; m++)
#pragma unroll
        for (int n = 0; n < 4; n++)
            g_xw1[(bi + ty * 4 + m) * HIDN + bj + tx * 4 + n] = acc[m][n];
}

// ---------------- 3. sim GEMM + spatial epilogue (store RAW score) ----------------
// raw = (lam*sim + (1-lam)*exp(-d2/5000)) * temperature   (sigmoid deferred)
__global__ __launch_bounds__(256) void k_sim(const float* __restrict__ pos,
                                             const float* __restrict__ plam,
                                             const float* __restrict__ ptemp) {
    __shared__ float As[8][128];
    __shared__ float Bs[8][128];
    int tid = threadIdx.x;
    int bi = blockIdx.y * 128;
    int bj = blockIdx.x * 128;
    int lr = tid >> 1;
    int lc = (tid & 1) << 2;
    int tx = tid & 15, ty = tid >> 4;

    float acc[8][8];
#pragma unroll
    for (int m = 0; m < 8; m++)
#pragma unroll
        for (int n = 0; n < 8; n++) acc[m][n] = 0.f;

    const float* Abase = g_fn + (bi + lr) * FEATN + lc;
    const float* Bbase = g_fn + (bj + lr) * FEATN + lc;

    for (int k0 = 0; k0 < FEATN; k0 += 8) {
        float4 a = *(const float4*)(Abase + k0);
        float4 b = *(const float4*)(Bbase + k0);
        As[lc + 0][lr] = a.x; As[lc + 1][lr] = a.y;
        As[lc + 2][lr] = a.z; As[lc + 3][lr] = a.w;
        Bs[lc + 0][lr] = b.x; Bs[lc + 1][lr] = b.y;
        Bs[lc + 2][lr] = b.z; Bs[lc + 3][lr] = b.w;
        __syncthreads();
#pragma unroll
        for (int k = 0; k < 8; k++) {
            float ar[8], br[8];
#pragma unroll
            for (int m = 0; m < 8; m++) ar[m] = As[k][ty * 8 + m];
#pragma unroll
            for (int n = 0; n < 8; n++) br[n] = Bs[k][tx * 8 + n];
#pragma unroll
            for (int m = 0; m < 8; m++)
#pragma unroll
                for (int n = 0; n < 8; n++) acc[m][n] += ar[m] * br[n];
        }
        __syncthreads();
    }

    float lam = 1.0f / (1.0f + expf(-plam[0]));
    float T = ptemp[0];
    float oml = 1.0f - lam;

    float pix[8], piy[8], p2i[8], pjx[8], pjy[8], p2j[8];
#pragma unroll
    for (int m = 0; m < 8; m++) {
        int r = bi + ty * 8 + m;
        pix[m] = pos[2 * r]; piy[m] = pos[2 * r + 1];
        p2i[m] = pix[m] * pix[m] + piy[m] * piy[m];
    }
#pragma unroll
    for (int n = 0; n < 8; n++) {
        int c = bj + tx * 8 + n;
        pjx[n] = pos[2 * c]; pjy[n] = pos[2 * c + 1];
        p2j[n] = pjx[n] * pjx[n] + pjy[n] * pjy[n];
    }
#pragma unroll
    for (int m = 0; m < 8; m++) {
        size_t rowoff = (size_t)(bi + ty * 8 + m) * NN + bj + tx * 8;
#pragma unroll
        for (int n = 0; n < 8; n++) {
            float d2 = fmaxf(p2i[m] + p2j[n] -
                             2.0f * (pix[m] * pjx[n] + piy[m] * pjy[n]), 0.0f);
            float sp = __expf(-d2 * INV2SD2);
            g_adj[rowoff + n] = (lam * acc[m][n] + oml * sp) * T;
        }
    }
}

// ---------------- 4. row-wise exact top-20 via register binary-search select -----
// keys: monotone u32 mapping of float (value desc, tie -> smaller index wins)
__global__ __launch_bounds__(128) void k_topk() {
    int row = blockIdx.x, t = threadIdx.x;
    const float* r = g_adj + (size_t)row * NN;

    unsigned key[48];
#pragma unroll
    for (int k = 0; k < 48; k++) {
        unsigned b = __float_as_uint(r[t + k * 128]);
        key[k] = (b & 0x80000000u) ? ~b : (b | 0x80000000u);
    }

    __shared__ int scnt[4];
    __shared__ unsigned smm[8];

    // per-row min/max of keys to seed the search range
    unsigned kmin = key[0], kmax = key[0];
#pragma unroll
    for (int k = 1; k < 48; k++) {
        kmin = min(kmin, key[k]);
        kmax = max(kmax, key[k]);
    }
    for (int o = 16; o > 0; o >>= 1) {
        kmin = min(kmin, __shfl_down_sync(0xffffffffu, kmin, o));
        kmax = max(kmax, __shfl_down_sync(0xffffffffu, kmax, o));
    }
    if ((t & 31) == 0) { smm[t >> 5] = kmin; smm[4 + (t >> 5)] = kmax; }
    __syncthreads();
    unsigned lo = min(min(smm[0], smm[1]), min(smm[2], smm[3]));
    unsigned hi = max(max(smm[4], smm[5]), max(smm[6], smm[7]));
    if (hi != 0xffffffffu) hi += 1;   // exclusive upper bound
    __syncthreads();

    // binary search: invariant count(key >= lo) >= 20
    for (int it = 0; it < 34; it++) {
        if (hi - lo <= 1) break;
        unsigned mid = lo + ((hi - lo) >> 1);
        int c = 0;
#pragma unroll
        for (int k = 0; k < 48; k++) c += (key[k] >= mid) ? 1 : 0;
        for (int o = 16; o > 0; o >>= 1) c += __shfl_down_sync(0xffffffffu, c, o);
        if ((t & 31) == 0) scnt[t >> 5] = c;
        __syncthreads();
        int tot = scnt[0] + scnt[1] + scnt[2] + scnt[3];
        __syncthreads();
        if (tot >= 20) {
            lo = mid;
            if (tot <= 96) break;     // small enough candidate set
        } else {
            hi = mid;
        }
    }

    // gather candidates >= lo (packed key|~idx for exact tie ordering)
    __shared__ unsigned long long cand[CAPC];
    __shared__ int cnum;
    cand[t] = 0ull;
    if (t == 0) cnum = 0;
    __syncthreads();
#pragma unroll
    for (int k = 0; k < 48; k++) {
        if (key[k] >= lo) {
            int p = atomicAdd(&cnum, 1);
            if (p < CAPC)
                cand[p] = ((unsigned long long)key[k] << 32) |
                          (unsigned)(~(t + k * 128));
        }
    }
    __syncthreads();

    // warp 0: 20 rounds of argmax over candidates
    if (t < 32) {
        for (int it = 0; it < KNNN; it++) {
            unsigned long long best = 0ull;
            int bslot = 0;
#pragma unroll
            for (int s = 0; s < CAPC / 32; s++) {
                unsigned long long c = cand[t + s * 32];
                if (c > best) { best = c; bslot = t + s * 32; }
            }
#pragma unroll
            for (int o = 16; o > 0; o >>= 1) {
                unsigned long long b2 = __shfl_down_sync(0xffffffffu, best, o);
                int s2 = __shfl_down_sync(0xffffffffu, bslot, o);
                if (b2 > best) { best = b2; bslot = s2; }
            }
            bslot = __shfl_sync(0xffffffffu, bslot, 0);
            if (t == 0) {
                unsigned kk = (unsigned)(best >> 32);
                unsigned fb = (kk & 0x80000000u) ? (kk & 0x7fffffffu) : ~kk;
                float raw = __uint_as_float(fb);
                g_val[row * KNNN + it] = 1.0f / (1.0f + expf(-raw));
                g_idx[row * KNNN + it] = (int)(~(unsigned)(best & 0xffffffffu));
                cand[bslot] = 0ull;
            }
            __syncwarp();
        }
    }
}

// ---------------- 5. degrees (column sums of M = A_bin + I) ----------------
__global__ void k_deg_init() {
    int i = blockIdx.x * 256 + threadIdx.x;
    if (i < NN) g_deg[i] = 1.0f;
}
__global__ void k_deg_scatter() {
    int e = blockIdx.x * 256 + threadIdx.x;
    if (e < NN * KNNN) {
        if (g_val[e] > THRF) atomicAdd(&g_deg[g_idx[e]], 1.0f);
    }
}
__global__ void k_dinv() {
    int i = blockIdx.x * 256 + threadIdx.x;
    if (i < NN) g_dinv[i] = 1.0f / sqrtf(g_deg[i]);
}

// ---------------- 6. GCN layer 1: h = relu(Mn^T (XW1) + b1) ----------------
__global__ void k_acc_init() {
    int idx = blockIdx.x * 256 + threadIdx.x;
    int i = idx >> 8;
    g_acc[idx] = g_dinv[i] * g_xw1[idx];
}
__global__ __launch_bounds__(HIDN) void k_scatter1() {
    int i = blockIdx.x, f = threadIdx.x;
    __shared__ int   sj[KNNN];
    __shared__ float sw[KNNN];
    if (f < KNNN) { sj[f] = g_idx[i * KNNN + f]; sw[f] = g_val[i * KNNN + f]; }
    __syncthreads();
    float z = g_dinv[i] * g_xw1[i * HIDN + f];
#pragma unroll
    for (int k = 0; k < KNNN; k++) {
        if (sw[k] > THRF) atomicAdd(&g_acc[sj[k] * HIDN + f], z);
    }
}
__global__ void k_relu(const float* __restrict__ b1) {
    int idx = blockIdx.x * 256 + threadIdx.x;
    int i = idx >> 8, f = idx & 255;
    g_acc[idx] = fmaxf(g_dinv[i] * g_acc[idx] + b1[f], 0.0f);
}

// ---------------- 7. t1 = h @ W2 ----------------
__global__ __launch_bounds__(64) void k_hw2(const float* __restrict__ W2) {
    int i = blockIdx.x, t = threadIdx.x;
    __shared__ float sh[HIDN];
    for (int k = t; k < HIDN; k += 64) sh[k] = g_acc[i * HIDN + k];
    __syncthreads();
    if (t < KMN) {
        float s = 0.f;
#pragma unroll 8
        for (int k = 0; k < HIDN; k++) s += sh[k] * W2[k * KMN + t];
        g_t1[i * KMN + t] = s;
    }
}

// ---------------- 8. GCN layer 2 + softmax -> S ----------------
__global__ __launch_bounds__(64) void k_sacc_init() {
    int i = blockIdx.x, t = threadIdx.x;
    if (t < KMN) g_sacc[i * KMN + t] = g_dinv[i] * g_t1[i * KMN + t];
}
__global__ __launch_bounds__(64) void k_scatter2() {
    int i = blockIdx.x, t = threadIdx.x;
    __shared__ int   sj[KNNN];
    __shared__ float sw[KNNN];
    if (t < KNNN) { sj[t] = g_idx[i * KNNN + t]; sw[t] = g_val[i * KNNN + t]; }
    __syncthreads();
    if (t < KMN) {
        float z = g_dinv[i] * g_t1[i * KMN + t];
#pragma unroll
        for (int k = 0; k < KNNN; k++) {
            if (sw[k] > THRF) atomicAdd(&g_sacc[sj[k] * KMN + t], z);
        }
    }
}
__global__ __launch_bounds__(64) void k_softmax(const float* __restrict__ b2,
                                                float* __restrict__ S) {
    int i = blockIdx.x, t = threadIdx.x;
    __shared__ float red[64];
    float v = (t < KMN) ? g_dinv[i] * g_sacc[i * KMN + t] + b2[t] : -FLT_MAX;
    red[t] = v;
#pragma unroll
    for (int o = 32; o > 0; o >>= 1) {
        __syncthreads();
        if (t < o) red[t] = fmaxf(red[t], red[t + o]);
    }
    __syncthreads();
    float mx = red[0];
    __syncthreads();
    float e = (t < KMN) ? expf(v - mx) : 0.f;
    red[t] = e;
#pragma unroll
    for (int o = 32; o > 0; o >>= 1) {
        __syncthreads();
        if (t < o) red[t] += red[t + o];
    }
    __syncthreads();
    float inv = 1.0f / red[0];
    if (t < KMN) S[i * KMN + t] = e * inv;
}

// ---------------- 9. t2 = adj @ S (sparse, masked adj values) -----
__global__ __launch_bounds__(64) void k_adjS(const float* __restrict__ S) {
    int i = blockIdx.x, t = threadIdx.x;
    __shared__ int   sj[KNNN];
    __shared__ float sw[KNNN];
    if (t < KNNN) { sj[t] = g_idx[i * KNNN + t]; sw[t] = g_val[i * KNNN + t]; }
    __syncthreads();
    if (t < KMN) {
        float a = 0.f;
#pragma unroll
        for (int k = 0; k < KNNN; k++) a += sw[k] * S[sj[k] * KMN + t];
        g_t2[i * KMN + t] = a;
    }
}

// ---------------- 10. A_coarse = S^T @ t2 (partial per 128-row block) -------
__global__ __launch_bounds__(256) void k_Ac(const float* __restrict__ S) {
    int t = threadIdx.x;
    int r0 = blockIdx.x * 128;
    __shared__ float sS[KMN], sT[KMN];
    float acc[10];
    int c1[10], c2[10]; bool ok[10];
#pragma unroll
    for (int p = 0; p < 10; p++) {
        int e = t + p * 256;
        ok[p] = (e < KMN * KMN);
        c1[p] = ok[p] ? e / KMN : 0;
        c2[p] = ok[p] ? e % KMN : 0;
        acc[p] = 0.f;
    }
    for (int r = 0; r < 128; r++) {
        int i = r0 + r;
        if (t < KMN) sS[t] = S[i * KMN + t];
        else if (t >= 64 && t < 64 + KMN) sT[t - 64] = g_t2[i * KMN + t - 64];
        __syncthreads();
#pragma unroll
        for (int p = 0; p < 10; p++)
            if (ok[p]) acc[p] += sS[c1[p]] * sT[c2[p]];
        __syncthreads();
    }
#pragma unroll
    for (int p = 0; p < 10; p++)
        if (ok[p]) atomicAdd(&g_Ac[t + p * 256], acc[p]);
}

// ---------------- 11. X_t = S^T @ X (partials, 128-row x 128-feat blocks) ---
__global__ __launch_bounds__(256) void k_Xt(const float* __restrict__ X,
                                            const float* __restrict__ S,
                                            float* __restrict__ outXt) {
    int t = threadIdx.x;
    int fc = blockIdx.x * 128;
    int r0 = blockIdx.y * 128;
    int f = t & 127, ch = t >> 7;
    __shared__ float sS[KMN];
    __shared__ float sX[128];
    float acc[25];
#pragma unroll
    for (int c = 0; c < 25; c++) acc[c] = 0.f;
    for (int r = 0; r < 128; r++) {
        int i = r0 + r;
        if (t < KMN) sS[t] = S[i * KMN + t];
        if (t >= 128) sX[t - 128] = X[i * FEATN + fc + t - 128];
        __syncthreads();
        float xv = sX[f];
#pragma unroll
        for (int c = 0; c < 25; c++) acc[c] += sS[ch * 25 + c] * xv;
        __syncthreads();
    }
#pragma unroll
    for (int c = 0; c < 25; c++)
        atomicAdd(&outXt[(ch * 25 + c) * FEATN + fc + f], acc[c]);
}

// ---------------- 12. spatial loss: sum over bin edges (S_i.S_j)*d2 ---------
__global__ __launch_bounds__(256) void k_loss(const float* __restrict__ S,
                                              const float* __restrict__ pos) {
    int warp = (blockIdx.x * 256 + threadIdx.x) >> 5;
    int lane = threadIdx.x & 31;
    if (warp >= NN) return;
    int i = warp;
    float s0 = (lane < KMN) ? S[i * KMN + lane] : 0.f;
    bool has2 = (lane + 32 < KMN);
    float s1 = has2 ? S[i * KMN + lane + 32] : 0.f;
    float xi = pos[2 * i], yi = pos[2 * i + 1];
    float p2i = xi * xi + yi * yi;
    float lsum = 0.f; int cnt = 0;
#pragma unroll
    for (int k = 0; k < KNNN; k++) {
        float v = g_val[i * KNNN + k];
        if (v > THRF) {
            int j = g_idx[i * KNNN + k];
            float xj = pos[2 * j], yj = pos[2 * j + 1];
            float d2 = fmaxf(p2i + xj * xj + yj * yj -
                             2.0f * (xi * xj + yi * yj), 0.0f);
            float dp = s0 * ((lane < KMN) ? S[j * KMN + lane] : 0.f);
            if (has2) dp += s1 * S[j * KMN + lane + 32];
            lsum += d2 * dp;
            cnt++;
        }
    }
#pragma unroll
    for (int o = 16; o > 0; o >>= 1) lsum += __shfl_down_sync(0xffffffffu, lsum, o);
    if (lane == 0) {
        atomicAdd(&g_loss, lsum);
        atomicAdd(&g_E, (float)cnt);
    }
}

// ---------------- zero/init + finalize ----------------
__global__ void k_zero(float* __restrict__ outXt) {
    int idx = blockIdx.x * 256 + threadIdx.x;
    if (idx < KMN * FEATN) outXt[idx] = 0.f;
    if (idx < KMN * KMN) g_Ac[idx] = 0.f;
    if (idx == 0) { g_loss = 0.f; g_E = 0.f; }
}
__global__ void k_final(const float* __restrict__ psw,
                        const float* __restrict__ plam,
                        float* __restrict__ out) {
    int idx = blockIdx.x * 256 + threadIdx.x;
    const int offA = NN * KMN + KMN * FEATN;
    if (idx < KMN * KMN) {
        float a = g_Ac[idx];
        out[offA + idx] = (a > THRF) ? a : 0.f;
    }
    if (idx == 0) {
        out[offA + KMN * KMN] = psw[0] * g_loss / g_E;
        out[offA + KMN * KMN + 1] = 1.0f / (1.0f + expf(-plam[0]));
    }
}

// ---------------- launcher ----------------
extern "C" void kernel_launch(void* const* d_in, const int* in_sizes, int n_in,
                              void* d_out, int out_size) {
    const float* X    = (const float*)d_in[0];
    const float* pos  = (const float*)d_in[1];
    const float* lamw = (const float*)d_in[2];
    const float* temp = (const float*)d_in[3];
    const float* sw   = (const float*)d_in[4];
    const float* W1   = (const float*)d_in[5];
    const float* b1   = (const float*)d_in[6];
    const float* W2   = (const float*)d_in[7];
    const float* b2   = (const float*)d_in[8];
    float* out  = (float*)d_out;
    float* S    = out;              // [N, K]
    float* oXt  = out + NN * KMN;   // [K, FEAT]

    k_prep<<<NN, 128>>>(X);
    k_xw1<<<dim3(HIDN / 64, NN / 64), 256>>>(X, W1);
    k_sim<<<dim3(NN / 128, NN / 128), 256>>>(pos, lamw, temp);
    k_topk<<<NN, 128>>>();
    k_zero<<<(KMN * FEATN + 255) / 256, 256>>>(oXt);
    k_deg_init<<<NN / 256, 256>>>();
    k_deg_scatter<<<(NN * KNNN + 255) / 256, 256>>>();
    k_dinv<<<NN / 256, 256>>>();
    k_acc_init<<<(NN * HIDN) / 256, 256>>>();
    k_scatter1<<<NN, HIDN>>>();
    k_relu<<<(NN * HIDN) / 256, 256>>>(b1);
    k_hw2<<<NN, 64>>>(W2);
    k_sacc_init<<<NN, 64>>>();
    k_scatter2<<<NN, 64>>>();
    k_softmax<<<NN, 64>>>(b2, S);
    k_adjS<<<NN, 64>>>(S);
    k_Ac<<<NN / 128, 256>>>(S);
    k_Xt<<<dim3(FEATN / 128, NN / 128), 256>>>(X, S, oXt);
    k_loss<<<NN / 8, 256>>>(S, pos);
    k_final<<<(KMN * KMN + 255) / 256, 256>>>(sw, lamw, out);
}